// round 10
// baseline (speedup 1.0000x reference)
#include <cuda_runtime.h>
#include <cuda_bf16.h>

#define BINS 256
#define NCOPIES 16          // 2 sub-histograms per warp (selected by lane parity)
#define HIST_BLOCKS 1184    // 148 SMs x 8 blocks -> one wave at occupancy 8
#define HIST_THREADS 256
#define PF_DIST 8           // prefetch distance in strides (~4 iterations ahead)

// Scratch (device globals -> no allocation). Zero-initialized at module load;
// the last block resets them every launch, so every graph replay starts clean.
__device__ unsigned int g_hist[BINS];
__device__ unsigned int g_ticket;

__device__ __forceinline__ void prefetch_l2(const void* p) {
    asm volatile("prefetch.global.L2 [%0];" :: "l"(p));
}

__device__ __forceinline__ void bin_one(float x, unsigned int* hist) {
    // torch.histc over [-4,4]: x==4 -> last bin; outside ignored; NaN ignored.
    // |x| <= 4 is one FSETP (free |x| operand mod); fmaf(x,32,128) ==
    // round((x+4)*32) bit-exact (power-of-2 scale commutes with rounding).
    if (fabsf(x) <= 4.0f) {
        float t = fmaf(x, 32.0f, 128.0f);
        int idx = __float2int_rd(t);
        idx = min(idx, BINS - 1);
        atomicAdd(&hist[idx], 1u);
    }
}

__device__ __forceinline__ void bin4(float4 v, unsigned int* h) {
    bin_one(v.x, h);
    bin_one(v.y, h);
    bin_one(v.z, h);
    bin_one(v.w, h);
}

__global__ void __launch_bounds__(HIST_THREADS, 8)
hist_kernel(const float* __restrict__ x, long long n,
            float* __restrict__ out, int out_size) {
    __shared__ unsigned int sh[NCOPIES][BINS];
    __shared__ bool is_last;
    const int tid  = threadIdx.x;
    const int warp = tid >> 5;
    const int lane = tid & 31;
    unsigned int* wh = sh[(warp << 1) | (lane & 1)];

    // Zero shared histograms
    #pragma unroll
    for (int i = tid; i < NCOPIES * BINS; i += HIST_THREADS)
        ((unsigned int*)sh)[i] = 0u;
    __syncthreads();

    const long long n4 = n >> 2;
    const float4* __restrict__ x4 = (const float4*)x;
    const long long stride = (long long)gridDim.x * HIST_THREADS;
    long long i = (long long)blockIdx.x * HIST_THREADS + tid;

    // R7 winning structure (prefetch 2 ahead, bin 2) + an L2 prefetch stream
    // running PF_DIST strides ahead so demand LDGs become L2 hits.
    if (i + stride < n4) {
        float4 a = x4[i];
        float4 b = x4[i + stride];
        long long j = i + 2 * stride;
        const long long last = n4 - 1;
        for (; j + stride < n4; j += 2 * stride) {
            long long p0 = j + PF_DIST * stride;
            long long p1 = p0 + stride;
            prefetch_l2(x4 + (p0 < last ? p0 : last));
            prefetch_l2(x4 + (p1 < last ? p1 : last));
            float4 c = x4[j];
            float4 d = x4[j + stride];
            bin4(a, wh);
            bin4(b, wh);
            a = c;
            b = d;
        }
        bin4(a, wh);
        bin4(b, wh);
        i = j;
    }
    // Remainder float4s
    for (; i < n4; i += stride)
        bin4(x4[i], wh);

    // Scalar tail (n not multiple of 4) — block 0 only
    if (blockIdx.x == 0) {
        for (long long j = (n4 << 2) + tid; j < n; j += HIST_THREADS)
            bin_one(x[j], wh);
    }
    __syncthreads();

    // Reduce the copies, one gmem atomic per bin per block
    for (int b = tid; b < BINS; b += HIST_THREADS) {
        unsigned int s = 0;
        #pragma unroll
        for (int c = 0; c < NCOPIES; c++) s += sh[c][b];
        if (s) atomicAdd(&g_hist[b], s);
    }

    // Last-block-done protocol: final block writes the output and resets state.
    __threadfence();
    __syncthreads();
    if (tid == 0)
        is_last = (atomicAdd(&g_ticket, 1u) == (unsigned)gridDim.x - 1u);
    __syncthreads();

    if (is_last) {
        __threadfence();                 // make all blocks' g_hist atomics visible
        unsigned int v = g_hist[tid];
        g_hist[tid] = 0u;                // reset for next graph replay
        if (tid == 0) g_ticket = 0u;
        float fv = (float)v;
        // Reference returns (h, h): fill every 256-element chunk of out.
        for (int base = 0; base + tid < out_size; base += BINS)
            out[base + tid] = fv;
    }
}

extern "C" void kernel_launch(void* const* d_in, const int* in_sizes, int n_in,
                              void* d_out, int out_size) {
    const float* x = (const float*)d_in[0];
    long long n = (long long)in_sizes[0];
    float* out = (float*)d_out;

    hist_kernel<<<HIST_BLOCKS, HIST_THREADS>>>(x, n, out, out_size);
}

// round 11
// speedup vs baseline: 2.0214x; 2.0214x over previous
#include <cuda_runtime.h>
#include <cuda_bf16.h>
#include <cstdint>

#define BINS 256
#define NCOP 8              // one smem histogram copy per warp
#define HIST_BLOCKS 1184    // 148 SMs x 8 blocks -> one wave at occupancy 8
#define HIST_THREADS 256

// Scratch (device globals -> no allocation). Zero-initialized at module load;
// the last block resets them every launch, so every graph replay starts clean.
__device__ unsigned int g_hist[BINS];
__device__ unsigned int g_ticket;

__device__ __forceinline__ uint32_t smem_u32(const void* p) {
    return (uint32_t)__cvta_generic_to_shared(p);
}
__device__ __forceinline__ void cp16(uint32_t dst, const void* src) {
    // 16B global->shared async copy, L1-bypass (.cg). No register destination,
    // no scoreboard: in-flight depth is decoupled from register pressure.
    asm volatile("cp.async.cg.shared.global [%0], [%1], 16;" :: "r"(dst), "l"(src));
}
#define CP_COMMIT() asm volatile("cp.async.commit_group;" ::: "memory")
#define CP_WAIT1()  asm volatile("cp.async.wait_group 1;" ::: "memory")
#define CP_WAIT0()  asm volatile("cp.async.wait_group 0;" ::: "memory")

__device__ __forceinline__ void bin_one(float x, unsigned int* hist) {
    // torch.histc over [-4,4]: x==4 -> last bin; outside/NaN ignored.
    // |x|<=4 is one FSETP; fmaf(x,32,128)==round((x+4)*32) bit-exact.
    if (fabsf(x) <= 4.0f) {
        float t = fmaf(x, 32.0f, 128.0f);
        int idx = __float2int_rd(t);
        idx = min(idx, BINS - 1);
        atomicAdd(&hist[idx], 1u);
    }
}
__device__ __forceinline__ void bin4(float4 v, unsigned int* h) {
    bin_one(v.x, h); bin_one(v.y, h); bin_one(v.z, h); bin_one(v.w, h);
}

__global__ void __launch_bounds__(HIST_THREADS, 8)
hist_kernel(const float* __restrict__ x, long long n,
            float* __restrict__ out, int out_size) {
    // Thread-private staging: thread t only ever writes/reads stg[s][q][t].
    // cp.async completion is tracked per-thread (wait_group), so the mainloop
    // needs NO block barriers at all.
    __shared__ float4 stg[2][2][HIST_THREADS];   // 16 KB
    __shared__ unsigned int sh[NCOP][BINS];      // 8 KB
    __shared__ bool is_last;

    const int tid  = threadIdx.x;
    const int warp = tid >> 5;
    unsigned int* wh = sh[warp];

    #pragma unroll
    for (int i = tid; i < NCOP * BINS; i += HIST_THREADS)
        ((unsigned int*)sh)[i] = 0u;
    __syncthreads();

    const long long n4 = n >> 2;
    const float4* __restrict__ x4 = (const float4*)x;
    const long long stride = (long long)gridDim.x * HIST_THREADS;
    long long i = (long long)blockIdx.x * HIST_THREADS + tid;

    const uint32_t s00 = smem_u32(&stg[0][0][tid]);
    const uint32_t s01 = smem_u32(&stg[0][1][tid]);
    const uint32_t s10 = smem_u32(&stg[1][0][tid]);
    const uint32_t s11 = smem_u32(&stg[1][1][tid]);

    if (i + 3 * stride < n4) {
        // Prologue: fill both stages (2 groups in flight).
        cp16(s00, x4 + i);              cp16(s01, x4 + i + stride);     CP_COMMIT();
        cp16(s10, x4 + i + 2 * stride); cp16(s11, x4 + i + 3 * stride); CP_COMMIT();
        long long next = i + 4 * stride;
        int cur = 0;
        while (next + stride < n4) {
            CP_WAIT1();                          // oldest group (stage cur) done
            float4 a = stg[cur][0][tid];
            float4 b = stg[cur][1][tid];
            bin4(a, wh);
            bin4(b, wh);
            // Refill stage cur with the next pair (LDS above completes ~29cyc,
            // the async smem write lands only after the ~500cyc gmem fetch).
            cp16(cur ? s10 : s00, x4 + next);
            cp16(cur ? s11 : s01, x4 + next + stride);
            CP_COMMIT();
            next += 2 * stride;
            cur ^= 1;
        }
        // Drain the two in-flight groups (oldest = stage cur).
        CP_WAIT1();
        bin4(stg[cur][0][tid], wh);
        bin4(stg[cur][1][tid], wh);
        CP_WAIT0();
        bin4(stg[cur ^ 1][0][tid], wh);
        bin4(stg[cur ^ 1][1][tid], wh);
        i = next;
    }
    // Ragged remainder (0..a few strides per thread): direct loads.
    for (; i < n4; i += stride)
        bin4(x4[i], wh);

    // Scalar tail (n not multiple of 4) — block 0 only.
    if (blockIdx.x == 0) {
        for (long long j = (n4 << 2) + tid; j < n; j += HIST_THREADS)
            bin_one(x[j], wh);
    }
    __syncthreads();

    // Reduce the copies, one gmem atomic per bin per block.
    for (int b = tid; b < BINS; b += HIST_THREADS) {
        unsigned int s = 0;
        #pragma unroll
        for (int c = 0; c < NCOP; c++) s += sh[c][b];
        if (s) atomicAdd(&g_hist[b], s);
    }

    // Last-block finalize: write output, reset globals for next graph replay.
    __threadfence();
    __syncthreads();
    if (tid == 0)
        is_last = (atomicAdd(&g_ticket, 1u) == (unsigned)gridDim.x - 1u);
    __syncthreads();

    if (is_last) {
        __threadfence();
        unsigned int v = g_hist[tid];
        g_hist[tid] = 0u;
        if (tid == 0) g_ticket = 0u;
        float fv = (float)v;
        for (int base = 0; base + tid < out_size; base += BINS)
            out[base + tid] = fv;   // reference returns (h, h)
    }
}

extern "C" void kernel_launch(void* const* d_in, const int* in_sizes, int n_in,
                              void* d_out, int out_size) {
    const float* x = (const float*)d_in[0];
    long long n = (long long)in_sizes[0];
    float* out = (float*)d_out;

    hist_kernel<<<HIST_BLOCKS, HIST_THREADS>>>(x, n, out, out_size);
}

// round 12
// speedup vs baseline: 2.0310x; 1.0048x over previous
#include <cuda_runtime.h>
#include <cuda_bf16.h>
#include <cstdint>

#define BINS 256
#define NCOPIES 16          // 2 sub-histograms per warp (selected by lane parity)
#define HIST_BLOCKS 1184    // 148 SMs x 8 blocks -> one wave at occupancy 8
#define HIST_THREADS 256

// Scratch (device globals -> no allocation). Zero-initialized at module load;
// the last block resets them every launch, so every graph replay starts clean.
__device__ unsigned int g_hist[BINS];
__device__ unsigned int g_ticket;

struct F8 { float v[8]; };

// 256-bit global load (LDG.E.256, sm_100+). One instruction, 32B in flight.
__device__ __forceinline__ F8 ld8(const float* p) {
    F8 r;
    asm volatile("ld.global.v8.f32 {%0,%1,%2,%3,%4,%5,%6,%7}, [%8];"
                 : "=f"(r.v[0]), "=f"(r.v[1]), "=f"(r.v[2]), "=f"(r.v[3]),
                   "=f"(r.v[4]), "=f"(r.v[5]), "=f"(r.v[6]), "=f"(r.v[7])
                 : "l"(p));
    return r;
}

__device__ __forceinline__ void bin_one(float x, unsigned int* hist) {
    // torch.histc over [-4,4]: x==4 -> last bin; outside/NaN ignored.
    // |x|<=4 is one FSETP (free |x| mod); fmaf(x,32,128)==round((x+4)*32)
    // bit-exact (power-of-2 scale commutes with rounding).
    if (fabsf(x) <= 4.0f) {
        float t = fmaf(x, 32.0f, 128.0f);
        int idx = __float2int_rd(t);
        idx = min(idx, BINS - 1);
        atomicAdd(&hist[idx], 1u);
    }
}

__device__ __forceinline__ void bin8(const F8& a, unsigned int* h) {
    #pragma unroll
    for (int k = 0; k < 8; k++) bin_one(a.v[k], h);
}

__global__ void __launch_bounds__(HIST_THREADS, 8)
hist_kernel(const float* __restrict__ x, long long n,
            float* __restrict__ out, int out_size) {
    __shared__ unsigned int sh[NCOPIES][BINS];
    __shared__ bool is_last;
    const int tid  = threadIdx.x;
    const int warp = tid >> 5;
    const int lane = tid & 31;
    unsigned int* wh = sh[(warp << 1) | (lane & 1)];

    #pragma unroll
    for (int i = tid; i < NCOPIES * BINS; i += HIST_THREADS)
        ((unsigned int*)sh)[i] = 0u;
    __syncthreads();

    const long long n8 = n >> 3;                 // float8 groups
    const long long stride = (long long)gridDim.x * HIST_THREADS;
    long long i = (long long)blockIdx.x * HIST_THREADS + tid;

    // Rolling depth-2 pipeline of 256-bit loads: while bin8(a) runs, the loads
    // for b and c (64 B/thread) are in flight. 3 live buffers = 24 data regs.
    if (i + 2 * stride < n8) {
        F8 a = ld8(x + 8 * i);
        F8 b = ld8(x + 8 * (i + stride));
        long long j = i + 2 * stride;
        for (; j < n8; j += stride) {
            F8 c = ld8(x + 8 * j);
            bin8(a, wh);
            a = b;
            b = c;
        }
        bin8(a, wh);
        bin8(b, wh);
        i = j;                                   // past end; loop below no-op
    } else {
        for (; i < n8; i += stride)
            bin8(ld8(x + 8 * i), wh);
    }

    // Scalar tail (n not multiple of 8) — block 0 only.
    if (blockIdx.x == 0) {
        for (long long j = (n8 << 3) + tid; j < n; j += HIST_THREADS)
            bin_one(x[j], wh);
    }
    __syncthreads();

    // Reduce the copies, one gmem atomic per bin per block.
    for (int b = tid; b < BINS; b += HIST_THREADS) {
        unsigned int s = 0;
        #pragma unroll
        for (int c = 0; c < NCOPIES; c++) s += sh[c][b];
        if (s) atomicAdd(&g_hist[b], s);
    }

    // Last-block finalize: write output, reset globals for next graph replay.
    __threadfence();
    __syncthreads();
    if (tid == 0)
        is_last = (atomicAdd(&g_ticket, 1u) == (unsigned)gridDim.x - 1u);
    __syncthreads();

    if (is_last) {
        __threadfence();
        unsigned int v = g_hist[tid];
        g_hist[tid] = 0u;
        if (tid == 0) g_ticket = 0u;
        float fv = (float)v;
        for (int base = 0; base + tid < out_size; base += BINS)
            out[base + tid] = fv;   // reference returns (h, h)
    }
}

extern "C" void kernel_launch(void* const* d_in, const int* in_sizes, int n_in,
                              void* d_out, int out_size) {
    const float* x = (const float*)d_in[0];
    long long n = (long long)in_sizes[0];
    float* out = (float*)d_out;

    hist_kernel<<<HIST_BLOCKS, HIST_THREADS>>>(x, n, out, out_size);
}